// round 4
// baseline (speedup 1.0000x reference)
#include <cuda_runtime.h>
#include <cuda_bf16.h>

// Problem constants
#define NTOK 8192
#define CDIM 1024
#define HDIM 2048
#define NEXP 8
#define RDIM 16

// GEMM tiling
#define BM 128
#define BN 128
#define BK 32
#define NSTG 2    // cp.async pipeline stages
#define AKP 40    // A smem row stride (bf16), 80B: cp.async-aligned, conflict-free ldmatrix
#define BNP 136   // B smem row stride, 272B

#define A_PLANE_B (BM * AKP * 2)   // 10240 bytes
#define B_PLANE_B (BK * BNP * 2)   // 8704 bytes
#define BS_BASE   (NSTG * 2 * A_PLANE_B)            // 40960
#define SMEM_TOT  (BS_BASE + NSTG * 2 * B_PLANE_B)  // 75776

// -------- scratch (device globals; no allocations allowed) --------
// split-bf16: hi = bf16(v), lo = bf16(v - hi)
__device__ __nv_bfloat16 g_W1h[(size_t)NEXP * CDIM * HDIM];
__device__ __nv_bfloat16 g_W1l[(size_t)NEXP * CDIM * HDIM];
__device__ __nv_bfloat16 g_W2h[(size_t)NEXP * HDIM * CDIM];
__device__ __nv_bfloat16 g_W2l[(size_t)NEXP * HDIM * CDIM];
__device__ __nv_bfloat16 g_xh[(size_t)NTOK * CDIM];
__device__ __nv_bfloat16 g_xl[(size_t)NTOK * CDIM];
__device__ __nv_bfloat16 g_hh[(size_t)NTOK * HDIM];
__device__ __nv_bfloat16 g_hl[(size_t)NTOK * HDIM];
__device__ float g_score[NTOK];
__device__ int   g_idx[NTOK];
__device__ int   g_tok[NTOK];
__device__ int   g_off[NEXP + 1];
__device__ int   g_cnt[NEXP];
__device__ int   g_cnt2[NEXP];
__device__ float g_wgn[NEXP * RDIM];

__device__ __forceinline__ float gelu_exact(float x) {
    return 0.5f * x * (1.0f + erff(x * 0.70710678118654752f));
}

__device__ __forceinline__ unsigned smem_u32(const void* p) {
    return (unsigned)__cvta_generic_to_shared(p);
}

__device__ __forceinline__ void split2(float a, float b,
                                       __nv_bfloat162& hi, __nv_bfloat162& lo) {
    __nv_bfloat16 ah = __float2bfloat16_rn(a);
    __nv_bfloat16 bh = __float2bfloat16_rn(b);
    hi = __nv_bfloat162(ah, bh);
    lo = __nv_bfloat162(__float2bfloat16_rn(a - __bfloat162float(ah)),
                        __float2bfloat16_rn(b - __bfloat162float(bh)));
}

// -------- kernel 1: normalize wg rows, zero counters --------
__global__ void init_kernel(const float* __restrict__ wg) {
    int t = threadIdx.x;
    if (t < NEXP) {
        g_cnt[t] = 0;
        g_cnt2[t] = 0;
        float s = 0.f;
        #pragma unroll
        for (int r = 0; r < RDIM; r++) { float v = wg[t * RDIM + r]; s += v * v; }
        float nrm = fmaxf(sqrtf(s), 1e-4f);
        #pragma unroll
        for (int r = 0; r < RDIM; r++) g_wgn[t * RDIM + r] = wg[t * RDIM + r] / nrm;
    }
}

// -------- kernel 2: convert W1, W2 to split-bf16 --------
__global__ void convert_kernel(const float4* __restrict__ W1, const float4* __restrict__ W2) {
    const int n14 = NEXP * CDIM * HDIM / 4;   // 4194304
    const int tot = 2 * n14;
    for (int i = blockIdx.x * blockDim.x + threadIdx.x; i < tot; i += gridDim.x * blockDim.x) {
        float4 v;
        __nv_bfloat162 *dh, *dl;
        if (i < n14) {
            v = W1[i];
            dh = (__nv_bfloat162*)g_W1h + (size_t)i * 2;
            dl = (__nv_bfloat162*)g_W1l + (size_t)i * 2;
        } else {
            int j = i - n14;
            v = W2[j];
            dh = (__nv_bfloat162*)g_W2h + (size_t)j * 2;
            dl = (__nv_bfloat162*)g_W2l + (size_t)j * 2;
        }
        __nv_bfloat162 h0, l0, h1, l1;
        split2(v.x, v.y, h0, l0);
        split2(v.z, v.w, h1, l1);
        dh[0] = h0; dh[1] = h1;
        dl[0] = l0; dl[1] = l1;
    }
}

// -------- kernel 3: gating (one warp per token, fp32 exact) --------
__global__ void gating_kernel(const float* __restrict__ x, const float* __restrict__ Wr) {
    int warp = threadIdx.x >> 5, lane = threadIdx.x & 31;
    int t = blockIdx.x * 8 + warp;

    const float4* xr = (const float4*)(x + (size_t)t * CDIM);
    const float4* wr4 = (const float4*)Wr;

    float acc[RDIM];
    #pragma unroll
    for (int r = 0; r < RDIM; r++) acc[r] = 0.f;

    for (int i = lane; i < CDIM / 4; i += 32) {
        float4 xv = xr[i];
        #pragma unroll
        for (int r = 0; r < RDIM; r++) {
            float4 wv = wr4[r * (CDIM / 4) + i];
            acc[r] += xv.x * wv.x + xv.y * wv.y + xv.z * wv.z + xv.w * wv.w;
        }
    }
    #pragma unroll
    for (int r = 0; r < RDIM; r++) {
        #pragma unroll
        for (int o = 16; o; o >>= 1) acc[r] += __shfl_xor_sync(0xFFFFFFFFu, acc[r], o);
    }
    if (lane < NEXP) {
        float l = 0.f;
        #pragma unroll
        for (int r = 0; r < RDIM; r++) l += acc[r] * g_wgn[lane * RDIM + r];

        float m = l; int bi = lane;
        #pragma unroll
        for (int o = 4; o; o >>= 1) {
            float om = __shfl_xor_sync(0xFFu, m, o);
            int   ob = __shfl_xor_sync(0xFFu, bi, o);
            if (om > m || (om == m && ob < bi)) { m = om; bi = ob; }
        }
        float es = expf(l - m);
        #pragma unroll
        for (int o = 4; o; o >>= 1) es += __shfl_xor_sync(0xFFu, es, o);
        if (lane == 0) {
            g_score[t] = 1.0f / es;
            g_idx[t] = bi;
            atomicAdd(&g_cnt[bi], 1);
        }
    }
}

// -------- kernel 4: tiny exclusive scan --------
__global__ void scan_kernel() {
    g_off[0] = 0;
    for (int e = 0; e < NEXP; e++) g_off[e + 1] = g_off[e] + g_cnt[e];
}

// -------- kernel 5: scatter tokens by expert, gather x -> split-bf16 --------
__global__ void gather_kernel(const float* __restrict__ x) {
    int warp = threadIdx.x >> 5, lane = threadIdx.x & 31;
    int t = blockIdx.x * 8 + warp;
    int pos = 0;
    if (lane == 0) {
        int e = g_idx[t];
        pos = g_off[e] + atomicAdd(&g_cnt2[e], 1);
        g_tok[pos] = t;
    }
    pos = __shfl_sync(0xFFFFFFFFu, pos, 0);
    const float4* xr = (const float4*)(x + (size_t)t * CDIM);
    __nv_bfloat162* dh = (__nv_bfloat162*)(g_xh + (size_t)pos * CDIM);
    __nv_bfloat162* dl = (__nv_bfloat162*)(g_xl + (size_t)pos * CDIM);
    for (int i = lane; i < CDIM / 4; i += 32) {
        float4 v = xr[i];
        __nv_bfloat162 h0, l0, h1, l1;
        split2(v.x, v.y, h0, l0);
        split2(v.z, v.w, h1, l1);
        dh[i * 2] = h0; dh[i * 2 + 1] = h1;
        dl[i * 2] = l0; dl[i * 2 + 1] = l1;
    }
}

// -------- GEMM core: split-bf16 (3-term) mma.sync m16n8k16, cp.async pipeline --------
// MODE 0: h = gelu(x @ W1[e] + b1[e]) -> g_hh/g_hl (split-bf16)
// MODE 1: out[tok] = (h @ W2[e] + b2[e]) * score[tok] (fp32, scattered)
#define CP16(dst, src) asm volatile("cp.async.cg.shared.global [%0],[%1],16;\n" ::"r"(dst), "l"(src))

#define LDSM_A(dst, addr)                                                          \
    asm volatile("ldmatrix.sync.aligned.m8n8.x4.shared.b16 {%0,%1,%2,%3},[%4];"    \
                 : "=r"(dst[0]), "=r"(dst[1]), "=r"(dst[2]), "=r"(dst[3])          \
                 : "r"(addr))
#define LDSM_BT(dst, addr)                                                             \
    asm volatile("ldmatrix.sync.aligned.m8n8.x4.trans.shared.b16 {%0,%1,%2,%3},[%4];" \
                 : "=r"(dst[0]), "=r"(dst[1]), "=r"(dst[2]), "=r"(dst[3])              \
                 : "r"(addr))

template <int K, int NT, int MODE>
__global__ void __launch_bounds__(128, 2)
gemm_kernel(const float* __restrict__ bias_all, float* __restrict__ out) {
    extern __shared__ char smem_raw[];
    // As[stage][plane]: BM x AKP bf16; Bs[stage][plane]: BK x BNP bf16
    auto As = [&](int s, int p) -> __nv_bfloat16* {
        return (__nv_bfloat16*)(smem_raw + (s * 2 + p) * A_PLANE_B);
    };
    auto Bs = [&](int s, int p) -> __nv_bfloat16* {
        return (__nv_bfloat16*)(smem_raw + BS_BASE + (s * 2 + p) * B_PLANE_B);
    };

    // map blockIdx.x -> (expert, row tile)
    int bt = blockIdx.x;
    int e = -1, m0 = 0, rows = 0;
    #pragma unroll
    for (int ee = 0; ee < NEXP; ee++) {
        if (e < 0) {
            int beg = g_off[ee], cnt = g_off[ee + 1] - beg;
            int nt = (cnt + BM - 1) / BM;
            if (bt < nt) { e = ee; m0 = beg + bt * BM; rows = min(BM, cnt - bt * BM); }
            else bt -= nt;
        }
    }
    if (e < 0) return;

    const __nv_bfloat16* Ah = (MODE == 0) ? g_xh : g_hh;
    const __nv_bfloat16* Al = (MODE == 0) ? g_xl : g_hl;
    const __nv_bfloat16* Bh = ((MODE == 0) ? g_W1h : g_W2h) + (size_t)e * K * NT;
    const __nv_bfloat16* Bl = ((MODE == 0) ? g_W1l : g_W2l) + (size_t)e * K * NT;
    const float* bias = bias_all + e * NT;
    const int n0 = blockIdx.y * BN;
    const int tid = threadIdx.x;
    const int warp = tid >> 5, lane = tid & 31;
    const int wm0 = (warp & 1) * 64, wn0 = (warp >> 1) * 64;
    const int g = lane >> 2, tq = lane & 3;

    const int lm_r = (lane & 7) + ((lane >> 3) & 1) * 8;
    const int lm_c = (lane >> 4) * 8;

    float acc[4][8][4];
    #pragma unroll
    for (int i = 0; i < 4; i++)
        #pragma unroll
        for (int j = 0; j < 8; j++)
            #pragma unroll
            for (int k = 0; k < 4; k++) acc[i][j][k] = 0.f;

    auto load_stage = [&](int kt, int buf) {
        int k0 = kt * BK;
        #pragma unroll
        for (int i = 0; i < 4; i++) {
            int idx = tid + i * 128;
            int r2 = idx >> 2, c2 = (idx & 3) * 8;
            int gr2 = m0 + r2; gr2 = gr2 < NTOK ? gr2 : NTOK - 1;  // clamp tail rows
            const size_t ao = (size_t)gr2 * K + k0 + c2;
            CP16(smem_u32(As(buf, 0) + r2 * AKP + c2), Ah + ao);
            CP16(smem_u32(As(buf, 1) + r2 * AKP + c2), Al + ao);
            int kr2 = idx >> 4, cb2 = (idx & 15) * 8;
            const size_t bo = (size_t)(k0 + kr2) * NT + n0 + cb2;
            CP16(smem_u32(Bs(buf, 0) + kr2 * BNP + cb2), Bh + bo);
            CP16(smem_u32(Bs(buf, 1) + kr2 * BNP + cb2), Bl + bo);
        }
        asm volatile("cp.async.commit_group;\n" ::: "memory");
    };

    auto mma_all = [&](unsigned (&a)[4][4], unsigned (&b)[4][4]) {
        #pragma unroll
        for (int im = 0; im < 4; im++) {
            #pragma unroll
            for (int in = 0; in < 8; in++) {
                unsigned b0 = b[in >> 1][(in & 1) * 2];
                unsigned b1 = b[in >> 1][(in & 1) * 2 + 1];
                asm volatile(
                    "mma.sync.aligned.m16n8k16.row.col.f32.bf16.bf16.f32 "
                    "{%0,%1,%2,%3},{%4,%5,%6,%7},{%8,%9},{%0,%1,%2,%3};"
                    : "+f"(acc[im][in][0]), "+f"(acc[im][in][1]),
                      "+f"(acc[im][in][2]), "+f"(acc[im][in][3])
                    : "r"(a[im][0]), "r"(a[im][1]), "r"(a[im][2]), "r"(a[im][3]),
                      "r"(b0), "r"(b1));
            }
        }
    };

    const int KT = K / BK;
    load_stage(0, 0);

    for (int kt = 0; kt < KT; kt++) {
        int buf = kt & 1;
        if (kt + 1 < KT) {
            load_stage(kt + 1, buf ^ 1);
            asm volatile("cp.async.wait_group 1;\n" ::: "memory");
        } else {
            asm volatile("cp.async.wait_group 0;\n" ::: "memory");
        }
        __syncthreads();

        #pragma unroll
        for (int kk = 0; kk < 2; kk++) {
            int kb = kk * 16;
            unsigned a[4][4], b[4][4];
            // term 1: Ah * Bh
            #pragma unroll
            for (int im = 0; im < 4; im++)
                LDSM_A(a[im], smem_u32(As(buf, 0) + (wm0 + im * 16 + lm_r) * AKP + kb + lm_c));
            #pragma unroll
            for (int in2 = 0; in2 < 4; in2++)
                LDSM_BT(b[in2], smem_u32(Bs(buf, 0) + (kb + lm_r) * BNP + wn0 + in2 * 16 + lm_c));
            mma_all(a, b);
            // term 2: Ah * Bl (reuse a)
            #pragma unroll
            for (int in2 = 0; in2 < 4; in2++)
                LDSM_BT(b[in2], smem_u32(Bs(buf, 1) + (kb + lm_r) * BNP + wn0 + in2 * 16 + lm_c));
            mma_all(a, b);
            // term 3: Al * Bh
            #pragma unroll
            for (int im = 0; im < 4; im++)
                LDSM_A(a[im], smem_u32(As(buf, 1) + (wm0 + im * 16 + lm_r) * AKP + kb + lm_c));
            #pragma unroll
            for (int in2 = 0; in2 < 4; in2++)
                LDSM_BT(b[in2], smem_u32(Bs(buf, 0) + (kb + lm_r) * BNP + wn0 + in2 * 16 + lm_c));
            mma_all(a, b);
        }
        __syncthreads();
    }

    // epilogue
    #pragma unroll
    for (int im = 0; im < 4; im++) {
        int r0 = wm0 + im * 16 + g;
        int r1 = r0 + 8;
        bool v0 = r0 < rows, v1 = r1 < rows;
        int tok0 = 0, tok1 = 0;
        float s0 = 0.f, s1 = 0.f;
        if (MODE == 1) {
            if (v0) { tok0 = g_tok[m0 + r0]; s0 = g_score[tok0]; }
            if (v1) { tok1 = g_tok[m0 + r1]; s1 = g_score[tok1]; }
        }
        #pragma unroll
        for (int in = 0; in < 8; in++) {
            int col = n0 + wn0 + in * 8 + tq * 2;
            float bv0 = bias[col], bv1 = bias[col + 1];
            if (MODE == 0) {
                if (v0) {
                    float a0 = gelu_exact(acc[im][in][0] + bv0);
                    float a1 = gelu_exact(acc[im][in][1] + bv1);
                    __nv_bfloat162 h, l;
                    split2(a0, a1, h, l);
                    size_t o = (size_t)(m0 + r0) * HDIM + col;
                    *(__nv_bfloat162*)&g_hh[o] = h;
                    *(__nv_bfloat162*)&g_hl[o] = l;
                }
                if (v1) {
                    float a2 = gelu_exact(acc[im][in][2] + bv0);
                    float a3 = gelu_exact(acc[im][in][3] + bv1);
                    __nv_bfloat162 h, l;
                    split2(a2, a3, h, l);
                    size_t o = (size_t)(m0 + r1) * HDIM + col;
                    *(__nv_bfloat162*)&g_hh[o] = h;
                    *(__nv_bfloat162*)&g_hl[o] = l;
                }
            } else {
                if (v0) {
                    *(float2*)&out[(size_t)tok0 * CDIM + col] =
                        make_float2((acc[im][in][0] + bv0) * s0, (acc[im][in][1] + bv1) * s0);
                }
                if (v1) {
                    *(float2*)&out[(size_t)tok1 * CDIM + col] =
                        make_float2((acc[im][in][2] + bv0) * s1, (acc[im][in][3] + bv1) * s1);
                }
            }
        }
    }
}

// -------- launch --------
extern "C" void kernel_launch(void* const* d_in, const int* in_sizes, int n_in,
                              void* d_out, int out_size) {
    const float* x  = (const float*)d_in[0];
    const float* Wr = (const float*)d_in[1];
    const float* wg = (const float*)d_in[2];
    const float* W1 = (const float*)d_in[3];
    const float* b1 = (const float*)d_in[4];
    const float* W2 = (const float*)d_in[5];
    const float* b2 = (const float*)d_in[6];
    float* out = (float*)d_out;

    const int MT = NTOK / BM + NEXP;  // 72 row tiles worst case

    cudaFuncSetAttribute(gemm_kernel<CDIM, HDIM, 0>,
                         cudaFuncAttributeMaxDynamicSharedMemorySize, SMEM_TOT);
    cudaFuncSetAttribute(gemm_kernel<HDIM, CDIM, 1>,
                         cudaFuncAttributeMaxDynamicSharedMemorySize, SMEM_TOT);

    init_kernel<<<1, 32>>>(wg);
    convert_kernel<<<8192, 256>>>((const float4*)W1, (const float4*)W2);
    gating_kernel<<<NTOK / 8, 256>>>(x, Wr);
    scan_kernel<<<1, 1>>>();
    gather_kernel<<<NTOK / 8, 256>>>(x);
    gemm_kernel<CDIM, HDIM, 0><<<dim3(MT, HDIM / BN), 128, SMEM_TOT>>>(b1, nullptr);
    gemm_kernel<HDIM, CDIM, 1><<<dim3(MT, CDIM / BN), 128, SMEM_TOT>>>(b2, out);
}

// round 9
// speedup vs baseline: 2.3750x; 2.3750x over previous
#include <cuda_runtime.h>
#include <cuda_fp16.h>

// Problem constants
#define NTOK 8192
#define CDIM 1024
#define HDIM 2048
#define NEXP 8
#define RDIM 16

// GEMM tiling
#define BM 128
#define BN 128
#define BK 32
#define NSTG 3    // cp.async pipeline stages
#define AKP 40    // A smem row stride (fp16), 80B: cp.async-aligned, conflict-free ldmatrix
#define BNP 136   // B smem row stride, 272B

#define A_PLANE_B (BM * AKP * 2)   // 10240 bytes
#define B_PLANE_B (BK * BNP * 2)   // 8704 bytes
#define BS_BASE   (NSTG * A_PLANE_B)            // 30720
#define SMEM_TOT  (BS_BASE + NSTG * B_PLANE_B)  // 56832

// -------- scratch (device globals; no allocations allowed) --------
__device__ __half g_W1f[(size_t)NEXP * CDIM * HDIM];
__device__ __half g_W2f[(size_t)NEXP * HDIM * CDIM];
__device__ __half g_xf[(size_t)NTOK * CDIM];
__device__ __half g_hf[(size_t)NTOK * HDIM];
__device__ float g_score[NTOK];
__device__ int   g_idx[NTOK];
__device__ int   g_tok[NTOK];
__device__ int   g_off[NEXP + 1];
__device__ int   g_cnt[NEXP];
__device__ int   g_cnt2[NEXP];
__device__ float g_wgn[NEXP * RDIM];

__device__ __forceinline__ float gelu_exact(float x) {
    return 0.5f * x * (1.0f + erff(x * 0.70710678118654752f));
}

__device__ __forceinline__ unsigned smem_u32(const void* p) {
    return (unsigned)__cvta_generic_to_shared(p);
}

// -------- kernel 1: normalize wg rows, zero counters --------
__global__ void init_kernel(const float* __restrict__ wg) {
    int t = threadIdx.x;
    if (t < NEXP) {
        g_cnt[t] = 0;
        g_cnt2[t] = 0;
        float s = 0.f;
        #pragma unroll
        for (int r = 0; r < RDIM; r++) { float v = wg[t * RDIM + r]; s += v * v; }
        float nrm = fmaxf(sqrtf(s), 1e-4f);
        #pragma unroll
        for (int r = 0; r < RDIM; r++) g_wgn[t * RDIM + r] = wg[t * RDIM + r] / nrm;
    }
}

// -------- kernel 2: convert W1, W2 to fp16 --------
__global__ void convert_kernel(const float4* __restrict__ W1, const float4* __restrict__ W2) {
    const int n14 = NEXP * CDIM * HDIM / 4;   // 4194304
    const int tot = 2 * n14;
    for (int i = blockIdx.x * blockDim.x + threadIdx.x; i < tot; i += gridDim.x * blockDim.x) {
        float4 v;
        __half2* dst;
        if (i < n14) {
            v = W1[i];
            dst = (__half2*)g_W1f + (size_t)i * 2;
        } else {
            int j = i - n14;
            v = W2[j];
            dst = (__half2*)g_W2f + (size_t)j * 2;
        }
        dst[0] = __floats2half2_rn(v.x, v.y);
        dst[1] = __floats2half2_rn(v.z, v.w);
    }
}

// -------- kernel 3: gating (one warp per token, fp32 exact) --------
__global__ void gating_kernel(const float* __restrict__ x, const float* __restrict__ Wr) {
    int warp = threadIdx.x >> 5, lane = threadIdx.x & 31;
    int t = blockIdx.x * 8 + warp;

    const float4* xr = (const float4*)(x + (size_t)t * CDIM);
    const float4* wr4 = (const float4*)Wr;

    float acc[RDIM];
    #pragma unroll
    for (int r = 0; r < RDIM; r++) acc[r] = 0.f;

    for (int i = lane; i < CDIM / 4; i += 32) {
        float4 xv = xr[i];
        #pragma unroll
        for (int r = 0; r < RDIM; r++) {
            float4 wv = wr4[r * (CDIM / 4) + i];
            acc[r] += xv.x * wv.x + xv.y * wv.y + xv.z * wv.z + xv.w * wv.w;
        }
    }
    #pragma unroll
    for (int r = 0; r < RDIM; r++) {
        #pragma unroll
        for (int o = 16; o; o >>= 1) acc[r] += __shfl_xor_sync(0xFFFFFFFFu, acc[r], o);
    }
    if (lane < NEXP) {
        float l = 0.f;
        #pragma unroll
        for (int r = 0; r < RDIM; r++) l += acc[r] * g_wgn[lane * RDIM + r];

        float m = l; int bi = lane;
        #pragma unroll
        for (int o = 4; o; o >>= 1) {
            float om = __shfl_xor_sync(0xFFu, m, o);
            int   ob = __shfl_xor_sync(0xFFu, bi, o);
            if (om > m || (om == m && ob < bi)) { m = om; bi = ob; }
        }
        float es = expf(l - m);
        #pragma unroll
        for (int o = 4; o; o >>= 1) es += __shfl_xor_sync(0xFFu, es, o);
        if (lane == 0) {
            g_score[t] = 1.0f / es;
            g_idx[t] = bi;
            atomicAdd(&g_cnt[bi], 1);
        }
    }
}

// -------- kernel 4: tiny exclusive scan --------
__global__ void scan_kernel() {
    g_off[0] = 0;
    for (int e = 0; e < NEXP; e++) g_off[e + 1] = g_off[e] + g_cnt[e];
}

// -------- kernel 5: scatter tokens by expert, gather x -> fp16 --------
__global__ void gather_kernel(const float* __restrict__ x) {
    int warp = threadIdx.x >> 5, lane = threadIdx.x & 31;
    int t = blockIdx.x * 8 + warp;
    int pos = 0;
    if (lane == 0) {
        int e = g_idx[t];
        pos = g_off[e] + atomicAdd(&g_cnt2[e], 1);
        g_tok[pos] = t;
    }
    pos = __shfl_sync(0xFFFFFFFFu, pos, 0);
    const float4* xr = (const float4*)(x + (size_t)t * CDIM);
    __half2* dst = (__half2*)(g_xf + (size_t)pos * CDIM);
    for (int i = lane; i < CDIM / 4; i += 32) {
        float4 v = xr[i];
        dst[i * 2]     = __floats2half2_rn(v.x, v.y);
        dst[i * 2 + 1] = __floats2half2_rn(v.z, v.w);
    }
}

// -------- GEMM core: fp16 mma.sync m16n8k16, cp.async 3-stage pipeline --------
// MODE 0: h = gelu(x @ W1[e] + b1[e]) -> g_hf (fp16)
// MODE 1: out[tok] = (h @ W2[e] + b2[e]) * score[tok] (fp32, scattered)
#define CP16(dst, src) asm volatile("cp.async.cg.shared.global [%0],[%1],16;\n" ::"r"(dst), "l"(src))

#define LDSM_A(dst, addr)                                                          \
    asm volatile("ldmatrix.sync.aligned.m8n8.x4.shared.b16 {%0,%1,%2,%3},[%4];"    \
                 : "=r"(dst[0]), "=r"(dst[1]), "=r"(dst[2]), "=r"(dst[3])          \
                 : "r"(addr))
#define LDSM_BT(dst, addr)                                                             \
    asm volatile("ldmatrix.sync.aligned.m8n8.x4.trans.shared.b16 {%0,%1,%2,%3},[%4];" \
                 : "=r"(dst[0]), "=r"(dst[1]), "=r"(dst[2]), "=r"(dst[3])              \
                 : "r"(addr))

template <int K, int NT, int MODE>
__global__ void __launch_bounds__(128, 2)
gemm_kernel(const float* __restrict__ bias_all, float* __restrict__ out) {
    extern __shared__ char smem_raw[];
    auto As = [&](int s) -> __half* { return (__half*)(smem_raw + s * A_PLANE_B); };
    auto Bs = [&](int s) -> __half* { return (__half*)(smem_raw + BS_BASE + s * B_PLANE_B); };

    // map blockIdx.x -> (expert, row tile)
    int bt = blockIdx.x;
    int e = -1, m0 = 0, rows = 0;
    #pragma unroll
    for (int ee = 0; ee < NEXP; ee++) {
        if (e < 0) {
            int beg = g_off[ee], cnt = g_off[ee + 1] - beg;
            int nt = (cnt + BM - 1) / BM;
            if (bt < nt) { e = ee; m0 = beg + bt * BM; rows = min(BM, cnt - bt * BM); }
            else bt -= nt;
        }
    }
    if (e < 0) return;

    const __half* A  = (MODE == 0) ? g_xf : g_hf;
    const __half* Bw = ((MODE == 0) ? g_W1f : g_W2f) + (size_t)e * K * NT;
    const float* bias = bias_all + e * NT;
    const int n0 = blockIdx.y * BN;
    const int tid = threadIdx.x;
    const int warp = tid >> 5, lane = tid & 31;
    const int wm0 = (warp & 1) * 64, wn0 = (warp >> 1) * 64;
    const int g = lane >> 2, tq = lane & 3;

    const int lm_r = (lane & 7) + ((lane >> 3) & 1) * 8;
    const int lm_c = (lane >> 4) * 8;

    float acc[4][8][4];
    #pragma unroll
    for (int i = 0; i < 4; i++)
        #pragma unroll
        for (int j = 0; j < 8; j++)
            #pragma unroll
            for (int k = 0; k < 4; k++) acc[i][j][k] = 0.f;

    auto load_stage = [&](int kt, int buf) {
        int k0 = kt * BK;
        #pragma unroll
        for (int i = 0; i < 4; i++) {
            int idx = tid + i * 128;
            int r = idx >> 2, c = (idx & 3) * 8;
            int gr = m0 + r; gr = gr < NTOK ? gr : NTOK - 1;  // clamp tail rows
            CP16(smem_u32(As(buf) + r * AKP + c), A + (size_t)gr * K + k0 + c);
            int kr = idx >> 4, cb = (idx & 15) * 8;
            CP16(smem_u32(Bs(buf) + kr * BNP + cb), Bw + (size_t)(k0 + kr) * NT + n0 + cb);
        }
        asm volatile("cp.async.commit_group;\n" ::: "memory");
    };

    const int KT = K / BK;
    load_stage(0, 0);
    load_stage(1, 1);

    for (int kt = 0; kt < KT; kt++) {
        int buf = kt % NSTG;
        if (kt + 2 < KT) {
            load_stage(kt + 2, (kt + 2) % NSTG);
            asm volatile("cp.async.wait_group 2;\n" ::: "memory");
        } else if (kt + 1 < KT) {
            asm volatile("cp.async.wait_group 1;\n" ::: "memory");
        } else {
            asm volatile("cp.async.wait_group 0;\n" ::: "memory");
        }
        __syncthreads();

        #pragma unroll
        for (int kk = 0; kk < 2; kk++) {
            int kb = kk * 16;
            unsigned a[4][4], b[4][4];
            #pragma unroll
            for (int im = 0; im < 4; im++)
                LDSM_A(a[im], smem_u32(As(buf) + (wm0 + im * 16 + lm_r) * AKP + kb + lm_c));
            #pragma unroll
            for (int in2 = 0; in2 < 4; in2++)
                LDSM_BT(b[in2], smem_u32(Bs(buf) + (kb + lm_r) * BNP + wn0 + in2 * 16 + lm_c));
            #pragma unroll
            for (int im = 0; im < 4; im++) {
                #pragma unroll
                for (int in = 0; in < 8; in++) {
                    unsigned b0 = b[in >> 1][(in & 1) * 2];
                    unsigned b1 = b[in >> 1][(in & 1) * 2 + 1];
                    asm volatile(
                        "mma.sync.aligned.m16n8k16.row.col.f32.f16.f16.f32 "
                        "{%0,%1,%2,%3},{%4,%5,%6,%7},{%8,%9},{%0,%1,%2,%3};"
                        : "+f"(acc[im][in][0]), "+f"(acc[im][in][1]),
                          "+f"(acc[im][in][2]), "+f"(acc[im][in][3])
                        : "r"(a[im][0]), "r"(a[im][1]), "r"(a[im][2]), "r"(a[im][3]),
                          "r"(b0), "r"(b1));
                }
            }
        }
        __syncthreads();
    }

    // epilogue
    #pragma unroll
    for (int im = 0; im < 4; im++) {
        int r0 = wm0 + im * 16 + g;
        int r1 = r0 + 8;
        bool v0 = r0 < rows, v1 = r1 < rows;
        int tok0 = 0, tok1 = 0;
        float s0 = 0.f, s1 = 0.f;
        if (MODE == 1) {
            if (v0) { tok0 = g_tok[m0 + r0]; s0 = g_score[tok0]; }
            if (v1) { tok1 = g_tok[m0 + r1]; s1 = g_score[tok1]; }
        }
        #pragma unroll
        for (int in = 0; in < 8; in++) {
            int col = n0 + wn0 + in * 8 + tq * 2;
            float bv0 = bias[col], bv1 = bias[col + 1];
            if (MODE == 0) {
                if (v0) {
                    float a0 = gelu_exact(acc[im][in][0] + bv0);
                    float a1 = gelu_exact(acc[im][in][1] + bv1);
                    *(__half2*)&g_hf[(size_t)(m0 + r0) * HDIM + col] = __floats2half2_rn(a0, a1);
                }
                if (v1) {
                    float a2 = gelu_exact(acc[im][in][2] + bv0);
                    float a3 = gelu_exact(acc[im][in][3] + bv1);
                    *(__half2*)&g_hf[(size_t)(m0 + r1) * HDIM + col] = __floats2half2_rn(a2, a3);
                }
            } else {
                if (v0) {
                    *(float2*)&out[(size_t)tok0 * CDIM + col] =
                        make_float2((acc[im][in][0] + bv0) * s0, (acc[im][in][1] + bv1) * s0);
                }
                if (v1) {
                    *(float2*)&out[(size_t)tok1 * CDIM + col] =
                        make_float2((acc[im][in][2] + bv0) * s1, (acc[im][in][3] + bv1) * s1);
                }
            }
        }
    }
}

// -------- launch --------
extern "C" void kernel_launch(void* const* d_in, const int* in_sizes, int n_in,
                              void* d_out, int out_size) {
    const float* x  = (const float*)d_in[0];
    const float* Wr = (const float*)d_in[1];
    const float* wg = (const float*)d_in[2];
    const float* W1 = (const float*)d_in[3];
    const float* b1 = (const float*)d_in[4];
    const float* W2 = (const float*)d_in[5];
    const float* b2 = (const float*)d_in[6];
    float* out = (float*)d_out;

    const int MT = NTOK / BM + NEXP;  // 72 row tiles worst case

    cudaFuncSetAttribute(gemm_kernel<CDIM, HDIM, 0>,
                         cudaFuncAttributeMaxDynamicSharedMemorySize, SMEM_TOT);
    cudaFuncSetAttribute(gemm_kernel<HDIM, CDIM, 1>,
                         cudaFuncAttributeMaxDynamicSharedMemorySize, SMEM_TOT);

    init_kernel<<<1, 32>>>(wg);
    convert_kernel<<<8192, 256>>>((const float4*)W1, (const float4*)W2);
    gating_kernel<<<NTOK / 8, 256>>>(x, Wr);
    scan_kernel<<<1, 1>>>();
    gather_kernel<<<NTOK / 8, 256>>>(x);
    gemm_kernel<CDIM, HDIM, 0><<<dim3(MT, HDIM / BN), 128, SMEM_TOT>>>(b1, nullptr);
    gemm_kernel<HDIM, CDIM, 1><<<dim3(MT, CDIM / BN), 128, SMEM_TOT>>>(b2, out);
}

// round 12
// speedup vs baseline: 2.4072x; 1.0135x over previous
#include <cuda_runtime.h>
#include <cuda_fp16.h>

// Problem constants
#define NTOK 8192
#define CDIM 1024
#define HDIM 2048
#define NEXP 8
#define RDIM 16

// GEMM tiling
#define BM 128
#define BN 128
#define BK 32
#define NSTG 3    // cp.async pipeline stages
#define AKP 40    // A smem row stride (fp16), 80B: cp.async-aligned, conflict-free ldmatrix
#define BNP 136   // B smem row stride, 272B

#define A_PLANE_B (BM * AKP * 2)   // 10240 bytes
#define B_PLANE_B (BK * BNP * 2)   // 8704 bytes
#define BS_BASE   (NSTG * A_PLANE_B)            // 30720
#define SMEM_TOT  (BS_BASE + NSTG * B_PLANE_B)  // 56832

// -------- scratch (device globals; no allocations allowed) --------
__device__ __half g_W1f[(size_t)NEXP * CDIM * HDIM];
__device__ __half g_W2f[(size_t)NEXP * HDIM * CDIM];
__device__ __half g_xf[(size_t)NTOK * CDIM];
__device__ __half g_hf[(size_t)NTOK * HDIM];
__device__ float g_score[NTOK];
__device__ int   g_idx[NTOK];
__device__ int   g_tok[NTOK];
__device__ int   g_off[NEXP + 1];
__device__ int   g_ctrs[17];     // [0..7]=cnt, [8..15]=cnt2, [16]=done-ticket

__device__ __forceinline__ float gelu_exact(float x) {
    return 0.5f * x * (1.0f + erff(x * 0.70710678118654752f));
}

__device__ __forceinline__ unsigned smem_u32(const void* p) {
    return (unsigned)__cvta_generic_to_shared(p);
}

// -------- convert kernels: W1 / W2 fp32 -> fp16 (run on forked stream) --------
__global__ void convW1_kernel(const float4* __restrict__ W1) {
    const int n4 = NEXP * CDIM * HDIM / 4;   // 4194304
    for (int i = blockIdx.x * blockDim.x + threadIdx.x; i < n4; i += gridDim.x * blockDim.x) {
        float4 v = W1[i];
        __half2* dst = (__half2*)g_W1f + (size_t)i * 2;
        dst[0] = __floats2half2_rn(v.x, v.y);
        dst[1] = __floats2half2_rn(v.z, v.w);
    }
}
__global__ void convW2_kernel(const float4* __restrict__ W2) {
    const int n4 = NEXP * HDIM * CDIM / 4;
    for (int i = blockIdx.x * blockDim.x + threadIdx.x; i < n4; i += gridDim.x * blockDim.x) {
        float4 v = W2[i];
        __half2* dst = (__half2*)g_W2f + (size_t)i * 2;
        dst[0] = __floats2half2_rn(v.x, v.y);
        dst[1] = __floats2half2_rn(v.z, v.w);
    }
}

// -------- gating (one warp per token, fp32 exact) + fused last-block scan --------
__global__ void gating_kernel(const float* __restrict__ x, const float* __restrict__ Wr,
                              const float* __restrict__ wg) {
    __shared__ float wgn_s[NEXP * RDIM];
    int tid = threadIdx.x;
    int warp = tid >> 5, lane = tid & 31;
    int t = blockIdx.x * 8 + warp;

    // per-block wg row normalization (identical fp32 math in every block)
    if (tid < NEXP) {
        float s = 0.f;
        #pragma unroll
        for (int r = 0; r < RDIM; r++) { float v = wg[tid * RDIM + r]; s += v * v; }
        float nrm = fmaxf(sqrtf(s), 1e-4f);
        #pragma unroll
        for (int r = 0; r < RDIM; r++) wgn_s[tid * RDIM + r] = wg[tid * RDIM + r] / nrm;
    }
    __syncthreads();

    const float4* xr = (const float4*)(x + (size_t)t * CDIM);
    const float4* wr4 = (const float4*)Wr;

    float acc[RDIM];
    #pragma unroll
    for (int r = 0; r < RDIM; r++) acc[r] = 0.f;

    for (int i = lane; i < CDIM / 4; i += 32) {
        float4 xv = xr[i];
        #pragma unroll
        for (int r = 0; r < RDIM; r++) {
            float4 wv = wr4[r * (CDIM / 4) + i];
            acc[r] += xv.x * wv.x + xv.y * wv.y + xv.z * wv.z + xv.w * wv.w;
        }
    }
    #pragma unroll
    for (int r = 0; r < RDIM; r++) {
        #pragma unroll
        for (int o = 16; o; o >>= 1) acc[r] += __shfl_xor_sync(0xFFFFFFFFu, acc[r], o);
    }
    if (lane < NEXP) {
        float l = 0.f;
        #pragma unroll
        for (int r = 0; r < RDIM; r++) l += acc[r] * wgn_s[lane * RDIM + r];

        float m = l; int bi = lane;
        #pragma unroll
        for (int o = 4; o; o >>= 1) {
            float om = __shfl_xor_sync(0xFFu, m, o);
            int   ob = __shfl_xor_sync(0xFFu, bi, o);
            if (om > m || (om == m && ob < bi)) { m = om; bi = ob; }
        }
        float es = expf(l - m);
        #pragma unroll
        for (int o = 4; o; o >>= 1) es += __shfl_xor_sync(0xFFu, es, o);
        if (lane == 0) {
            g_score[t] = 1.0f / es;
            g_idx[t] = bi;
            atomicAdd(&g_ctrs[bi], 1);
        }
    }

    // fused exclusive scan: last block to finish computes g_off
    __syncthreads();
    if (tid == 0) {
        __threadfence();
        int old = atomicAdd(&g_ctrs[16], 1);
        if (old == (int)gridDim.x - 1) {
            __threadfence();
            int a = 0;
            g_off[0] = 0;
            #pragma unroll
            for (int e = 0; e < NEXP; e++) {
                a += *(volatile int*)&g_ctrs[e];
                g_off[e + 1] = a;
            }
        }
    }
}

// -------- scatter tokens by expert, gather x -> fp16 --------
__global__ void gather_kernel(const float* __restrict__ x) {
    int warp = threadIdx.x >> 5, lane = threadIdx.x & 31;
    int t = blockIdx.x * 8 + warp;
    int pos = 0;
    if (lane == 0) {
        int e = g_idx[t];
        pos = g_off[e] + atomicAdd(&g_ctrs[8 + e], 1);
        g_tok[pos] = t;
    }
    pos = __shfl_sync(0xFFFFFFFFu, pos, 0);
    const float4* xr = (const float4*)(x + (size_t)t * CDIM);
    __half2* dst = (__half2*)(g_xf + (size_t)pos * CDIM);
    for (int i = lane; i < CDIM / 4; i += 32) {
        float4 v = xr[i];
        dst[i * 2]     = __floats2half2_rn(v.x, v.y);
        dst[i * 2 + 1] = __floats2half2_rn(v.z, v.w);
    }
}

// -------- GEMM core: fp16 mma.sync m16n8k16, cp.async 3-stage pipeline --------
// MODE 0: h = gelu(x @ W1[e] + b1[e]) -> g_hf (fp16)
// MODE 1: out[tok] = (h @ W2[e] + b2[e]) * score[tok] (fp32, scattered)
#define CP16(dst, src) asm volatile("cp.async.cg.shared.global [%0],[%1],16;\n" ::"r"(dst), "l"(src))

#define LDSM_A(dst, addr)                                                          \
    asm volatile("ldmatrix.sync.aligned.m8n8.x4.shared.b16 {%0,%1,%2,%3},[%4];"    \
                 : "=r"(dst[0]), "=r"(dst[1]), "=r"(dst[2]), "=r"(dst[3])          \
                 : "r"(addr))
#define LDSM_BT(dst, addr)                                                             \
    asm volatile("ldmatrix.sync.aligned.m8n8.x4.trans.shared.b16 {%0,%1,%2,%3},[%4];" \
                 : "=r"(dst[0]), "=r"(dst[1]), "=r"(dst[2]), "=r"(dst[3])              \
                 : "r"(addr))

template <int K, int NT, int MODE>
__global__ void __launch_bounds__(128, 2)
gemm_kernel(const float* __restrict__ bias_all, float* __restrict__ out) {
    extern __shared__ char smem_raw[];
    auto As = [&](int s) -> __half* { return (__half*)(smem_raw + s * A_PLANE_B); };
    auto Bs = [&](int s) -> __half* { return (__half*)(smem_raw + BS_BASE + s * B_PLANE_B); };

    // map blockIdx.x -> (expert, row tile)
    int bt = blockIdx.x;
    int e = -1, m0 = 0, rows = 0;
    #pragma unroll
    for (int ee = 0; ee < NEXP; ee++) {
        if (e < 0) {
            int beg = g_off[ee], cnt = g_off[ee + 1] - beg;
            int nt = (cnt + BM - 1) / BM;
            if (bt < nt) { e = ee; m0 = beg + bt * BM; rows = min(BM, cnt - bt * BM); }
            else bt -= nt;
        }
    }
    if (e < 0) return;

    const __half* A  = (MODE == 0) ? g_xf : g_hf;
    const __half* Bw = ((MODE == 0) ? g_W1f : g_W2f) + (size_t)e * K * NT;
    const float* bias = bias_all + e * NT;
    const int n0 = blockIdx.y * BN;
    const int tid = threadIdx.x;
    const int warp = tid >> 5, lane = tid & 31;
    const int wm0 = (warp & 1) * 64, wn0 = (warp >> 1) * 64;
    const int g = lane >> 2, tq = lane & 3;

    const int lm_r = (lane & 7) + ((lane >> 3) & 1) * 8;
    const int lm_c = (lane >> 4) * 8;

    float acc[4][8][4];
    #pragma unroll
    for (int i = 0; i < 4; i++)
        #pragma unroll
        for (int j = 0; j < 8; j++)
            #pragma unroll
            for (int k = 0; k < 4; k++) acc[i][j][k] = 0.f;

    auto load_stage = [&](int kt, int buf) {
        int k0 = kt * BK;
        #pragma unroll
        for (int i = 0; i < 4; i++) {
            int idx = tid + i * 128;
            int r = idx >> 2, c = (idx & 3) * 8;
            int gr = m0 + r; gr = gr < NTOK ? gr : NTOK - 1;  // clamp tail rows
            CP16(smem_u32(As(buf) + r * AKP + c), A + (size_t)gr * K + k0 + c);
            int kr = idx >> 4, cb = (idx & 15) * 8;
            CP16(smem_u32(Bs(buf) + kr * BNP + cb), Bw + (size_t)(k0 + kr) * NT + n0 + cb);
        }
        asm volatile("cp.async.commit_group;\n" ::: "memory");
    };

    const int KT = K / BK;
    load_stage(0, 0);
    load_stage(1, 1);

    for (int kt = 0; kt < KT; kt++) {
        int buf = kt % NSTG;
        if (kt + 2 < KT) {
            load_stage(kt + 2, (kt + 2) % NSTG);
            asm volatile("cp.async.wait_group 2;\n" ::: "memory");
        } else if (kt + 1 < KT) {
            asm volatile("cp.async.wait_group 1;\n" ::: "memory");
        } else {
            asm volatile("cp.async.wait_group 0;\n" ::: "memory");
        }
        __syncthreads();

        #pragma unroll
        for (int kk = 0; kk < 2; kk++) {
            int kb = kk * 16;
            unsigned a[4][4], b[4][4];
            #pragma unroll
            for (int im = 0; im < 4; im++)
                LDSM_A(a[im], smem_u32(As(buf) + (wm0 + im * 16 + lm_r) * AKP + kb + lm_c));
            #pragma unroll
            for (int in2 = 0; in2 < 4; in2++)
                LDSM_BT(b[in2], smem_u32(Bs(buf) + (kb + lm_r) * BNP + wn0 + in2 * 16 + lm_c));
            #pragma unroll
            for (int im = 0; im < 4; im++) {
                #pragma unroll
                for (int in = 0; in < 8; in++) {
                    unsigned b0 = b[in >> 1][(in & 1) * 2];
                    unsigned b1 = b[in >> 1][(in & 1) * 2 + 1];
                    asm volatile(
                        "mma.sync.aligned.m16n8k16.row.col.f32.f16.f16.f32 "
                        "{%0,%1,%2,%3},{%4,%5,%6,%7},{%8,%9},{%0,%1,%2,%3};"
                        : "+f"(acc[im][in][0]), "+f"(acc[im][in][1]),
                          "+f"(acc[im][in][2]), "+f"(acc[im][in][3])
                        : "r"(a[im][0]), "r"(a[im][1]), "r"(a[im][2]), "r"(a[im][3]),
                          "r"(b0), "r"(b1));
                }
            }
        }
        __syncthreads();
    }

    // epilogue
    #pragma unroll
    for (int im = 0; im < 4; im++) {
        int r0 = wm0 + im * 16 + g;
        int r1 = r0 + 8;
        bool v0 = r0 < rows, v1 = r1 < rows;
        int tok0 = 0, tok1 = 0;
        float s0 = 0.f, s1 = 0.f;
        if (MODE == 1) {
            if (v0) { tok0 = g_tok[m0 + r0]; s0 = g_score[tok0]; }
            if (v1) { tok1 = g_tok[m0 + r1]; s1 = g_score[tok1]; }
        }
        #pragma unroll
        for (int in = 0; in < 8; in++) {
            int col = n0 + wn0 + in * 8 + tq * 2;
            float bv0 = bias[col], bv1 = bias[col + 1];
            if (MODE == 0) {
                if (v0) {
                    float a0 = gelu_exact(acc[im][in][0] + bv0);
                    float a1 = gelu_exact(acc[im][in][1] + bv1);
                    *(__half2*)&g_hf[(size_t)(m0 + r0) * HDIM + col] = __floats2half2_rn(a0, a1);
                }
                if (v1) {
                    float a2 = gelu_exact(acc[im][in][2] + bv0);
                    float a3 = gelu_exact(acc[im][in][3] + bv1);
                    *(__half2*)&g_hf[(size_t)(m0 + r1) * HDIM + col] = __floats2half2_rn(a2, a3);
                }
            } else {
                if (v0) {
                    *(float2*)&out[(size_t)tok0 * CDIM + col] =
                        make_float2((acc[im][in][0] + bv0) * s0, (acc[im][in][1] + bv1) * s0);
                }
                if (v1) {
                    *(float2*)&out[(size_t)tok1 * CDIM + col] =
                        make_float2((acc[im][in][2] + bv0) * s1, (acc[im][in][3] + bv1) * s1);
                }
            }
        }
    }
}

// -------- launch: fork/join so weight conversion overlaps gating/gather/GEMM1 --------
extern "C" void kernel_launch(void* const* d_in, const int* in_sizes, int n_in,
                              void* d_out, int out_size) {
    const float* x  = (const float*)d_in[0];
    const float* Wr = (const float*)d_in[1];
    const float* wg = (const float*)d_in[2];
    const float* W1 = (const float*)d_in[3];
    const float* b1 = (const float*)d_in[4];
    const float* W2 = (const float*)d_in[5];
    const float* b2 = (const float*)d_in[6];
    float* out = (float*)d_out;

    const int MT = NTOK / BM + NEXP;  // 72 row tiles worst case

    // one-time setup on the first (uncaptured correctness) call
    static cudaStream_t s1 = nullptr;
    static cudaEvent_t ev_fork = nullptr, ev_w1 = nullptr, ev_w2 = nullptr;
    static int* ctrs_addr = nullptr;
    if (!s1) {
        cudaStreamCreateWithFlags(&s1, cudaStreamNonBlocking);
        cudaEventCreateWithFlags(&ev_fork, cudaEventDisableTiming);
        cudaEventCreateWithFlags(&ev_w1, cudaEventDisableTiming);
        cudaEventCreateWithFlags(&ev_w2, cudaEventDisableTiming);
        cudaGetSymbolAddress((void**)&ctrs_addr, g_ctrs);
        cudaFuncSetAttribute(gemm_kernel<CDIM, HDIM, 0>,
                             cudaFuncAttributeMaxDynamicSharedMemorySize, SMEM_TOT);
        cudaFuncSetAttribute(gemm_kernel<HDIM, CDIM, 1>,
                             cudaFuncAttributeMaxDynamicSharedMemorySize, SMEM_TOT);
    }

    // zero counters (cnt/cnt2/ticket)
    cudaMemsetAsync(ctrs_addr, 0, 17 * sizeof(int), 0);

    // fork: weight conversion on s1
    cudaEventRecord(ev_fork, 0);
    cudaStreamWaitEvent(s1, ev_fork, 0);
    convW1_kernel<<<4096, 256, 0, s1>>>((const float4*)W1);
    cudaEventRecord(ev_w1, s1);
    convW2_kernel<<<4096, 256, 0, s1>>>((const float4*)W2);
    cudaEventRecord(ev_w2, s1);

    // main chain: gating (+fused scan) -> gather
    gating_kernel<<<NTOK / 8, 256>>>(x, Wr, wg);
    gather_kernel<<<NTOK / 8, 256>>>(x);

    // join W1 before GEMM1, W2 before GEMM2
    cudaStreamWaitEvent(0, ev_w1, 0);
    gemm_kernel<CDIM, HDIM, 0><<<dim3(MT, HDIM / BN), 128, SMEM_TOT>>>(b1, nullptr);
    cudaStreamWaitEvent(0, ev_w2, 0);
    gemm_kernel<HDIM, CDIM, 1><<<dim3(MT, CDIM / BN), 128, SMEM_TOT>>>(b2, out);
}